// round 8
// baseline (speedup 1.0000x reference)
#include <cuda_runtime.h>
#include <cstdint>

// ---------------------------------------------------------------------------
// NoteAxis: 2-layer LSTM, B=4096, U=128, 128 steps, teacher-forced.
// Persistent fp32 kernel, fma.rn.f32x2 packing two output columns (a unit
// pair) per register; weights load as natural float2, x duplicated in SMEM.
// 128 CTAs x 256 threads; CTA owns 32 batch rows for all 128 steps.
// R8: manual 2-stage software pipeline in the GEMM inner loop — loads for
// iteration k+1 issue before the FMAs of iteration k, hiding the 29-cycle
// LDS latency that bound R5-R7.
// ---------------------------------------------------------------------------

#define B_TOTAL   4096
#define NSTEP     128
#define FDIM      127
#define UNITS     128
#define GATES     512
#define KDIM      256
#define BT        32
#define NCTA      (B_TOTAL / BT)       // 128
#define NTHREAD   256
#define KC        16                   // k rows per weight chunk
#define NCHUNK    (KDIM / KC)          // 16 per layer
#define SEQLEN    (2 * NCHUNK)         // 32 chunks per step (both layers)
#define CHUNK_FLOATS (KC * GATES)      // 8192
#define CHUNK_BYTES  (CHUNK_FLOATS * 4)// 32768

// x region: rows 0..127 = x_t, 128..255 = h0, 256..383 = h1.
// Each row: 32 batch values DUPLICATED ((v,v) f32 pairs) in 4 bank-swizzled
// slices of 8: slice s=b>>3 at byte offset s*64 + (s>>1)*16.
#define XROWF     68                   // floats per row (272 B)
#define XROWB     272
#define NXROW     384

// shared layout (float offsets)
#define OFF_X     0
#define OFF_W     (NXROW * XROWF)              // 26112
#define OFF_B0    (OFF_W + 3 * CHUNK_FLOATS)   // 50688
#define OFF_B1    (OFF_B0 + GATES)             // 51200
#define OFF_WO    (OFF_B1 + GATES)             // 51712
#define OFF_BO    (OFF_WO + UNITS)             // 51840
#define SMEM_FLOATS (OFF_BO + 4)               // 51844
#define SMEM_BYTES  (SMEM_FLOATS * 4)          // 207376 (~202.5 KB)

// ---------------- persistent device scratch (no runtime alloc) -------------
__device__ float g_Wt0[KDIM * GATES];   // [k][c] transposed
__device__ float g_Wt1[KDIM * GATES];
__device__ float g_b0[GATES];           // b_ih + b_hh
__device__ float g_b1[GATES];
__device__ float g_wout[UNITS];
__device__ float g_bout[1];

// ---------------------------------------------------------------------------
__global__ void noteaxis_prep(const float* __restrict__ wih0, const float* __restrict__ whh0,
                              const float* __restrict__ bih0, const float* __restrict__ bhh0,
                              const float* __restrict__ wih1, const float* __restrict__ whh1,
                              const float* __restrict__ bih1, const float* __restrict__ bhh1,
                              const float* __restrict__ wout, const float* __restrict__ bout)
{
    int idx = blockIdx.x * blockDim.x + threadIdx.x;
    if (idx < KDIM * GATES) {
        int k = idx >> 9;
        int c = idx & 511;
        g_Wt0[idx] = (k < UNITS) ? wih0[c * UNITS + k] : whh0[c * UNITS + (k - UNITS)];
        g_Wt1[idx] = (k < UNITS) ? wih1[c * UNITS + k] : whh1[c * UNITS + (k - UNITS)];
    }
    if (idx < GATES) {
        g_b0[idx] = bih0[idx] + bhh0[idx];
        g_b1[idx] = bih1[idx] + bhh1[idx];
    }
    if (idx < UNITS) g_wout[idx] = wout[idx];
    if (idx == 0)    g_bout[0]   = bout[0];
}

// ---------------------------------------------------------------------------
__device__ __forceinline__ float ftanh_(float x) {
    float r;
    asm("tanh.approx.f32 %0, %1;" : "=f"(r) : "f"(x));
    return r;
}
__device__ __forceinline__ float fsig(float x) {
    return fmaf(0.5f, ftanh_(0.5f * x), 0.5f);
}
__device__ __forceinline__ void unpack2(unsigned long long v, float& lo, float& hi) {
    asm("mov.b64 {%0, %1}, %2;" : "=f"(lo), "=f"(hi) : "l"(v));
}
__device__ __forceinline__ unsigned long long pack2(float lo, float hi) {
    unsigned long long v;
    asm("mov.b64 %0, {%1, %2};" : "=l"(v) : "f"(lo), "f"(hi));
    return v;
}

// byte offset of (dup'd) batch element b within an x row
__device__ __forceinline__ uint32_t bslice(int b) {
    int s = b >> 3;
    return (uint32_t)(s * 64 + (s >> 1) * 16 + (b & 7) * 8);
}

// Stage one KC x 512 weight chunk (32 KB) gmem -> smem via cp.async.cg.
__device__ __forceinline__ void prefetch_chunk(uint32_t dst_smem, const float* __restrict__ src, int tid) {
    const char* s = reinterpret_cast<const char*>(src) + tid * 16;
    uint32_t d = dst_smem + tid * 16;
#pragma unroll
    for (int r = 0; r < 8; ++r) {
        asm volatile("cp.async.cg.shared.global [%0], [%1], 16;" :: "r"(d), "l"(s) : "memory");
        d += NTHREAD * 16;
        s += NTHREAD * 16;
    }
    asm volatile("cp.async.commit_group;" ::: "memory");
}

__device__ __forceinline__ const float* chunk_src(int s) {   // s in 0..31
    return (s < NCHUNK) ? (g_Wt0 + (size_t)s * CHUNK_FLOATS)
                        : (g_Wt1 + (size_t)(s - NCHUNK) * CHUNK_FLOATS);
}

// one k-slice of operands
struct KOps {
    unsigned long long x[8];
    unsigned long long w[4];
};

__device__ __forceinline__ void load_k(uint32_t xaddr, uint32_t waddr, KOps& o) {
    asm volatile("ld.shared.v2.u64 {%0, %1}, [%2];" : "=l"(o.x[0]), "=l"(o.x[1]) : "r"(xaddr));
    asm volatile("ld.shared.v2.u64 {%0, %1}, [%2];" : "=l"(o.x[2]), "=l"(o.x[3]) : "r"(xaddr + 16));
    asm volatile("ld.shared.v2.u64 {%0, %1}, [%2];" : "=l"(o.x[4]), "=l"(o.x[5]) : "r"(xaddr + 32));
    asm volatile("ld.shared.v2.u64 {%0, %1}, [%2];" : "=l"(o.x[6]), "=l"(o.x[7]) : "r"(xaddr + 48));
    asm volatile("ld.shared.b64 %0, [%1];" : "=l"(o.w[0]) : "r"(waddr));
    asm volatile("ld.shared.b64 %0, [%1];" : "=l"(o.w[1]) : "r"(waddr + 512));
    asm volatile("ld.shared.b64 %0, [%1];" : "=l"(o.w[2]) : "r"(waddr + 1024));
    asm volatile("ld.shared.b64 %0, [%1];" : "=l"(o.w[3]) : "r"(waddr + 1536));
}

__device__ __forceinline__ void fma_k(const KOps& o, unsigned long long (&acc)[8][4]) {
#pragma unroll
    for (int g = 0; g < 4; ++g)
#pragma unroll
        for (int r = 0; r < 8; ++r)
            asm("fma.rn.f32x2 %0, %1, %2, %0;" : "+l"(acc[r][g]) : "l"(o.x[r]), "l"(o.w[g]));
}

// GEMM over one KC-k chunk, 2-stage software pipelined: loads for k+1 issue
// before the FMAs of k, so the 29-cycle LDS latency is covered by ~32 FMA
// issue slots instead of stalling every iteration.
__device__ __forceinline__ void gemm_chunk(uint32_t xaddr, uint32_t waddr,
                                           unsigned long long (&acc)[8][4])
{
    KOps a, b;
    load_k(xaddr, waddr, a);
#pragma unroll
    for (int kk = 0; kk < KC; kk += 2) {
        xaddr += XROWB;     waddr += GATES * 4;
        load_k(xaddr, waddr, b);          // prefetch k+1
        fma_k(a, acc);                    // consume k
        xaddr += XROWB;     waddr += GATES * 4;
        if (kk + 2 < KC) load_k(xaddr, waddr, a);   // prefetch k+2
        fma_k(b, acc);                    // consume k+1
    }
}

// Gates -> nonlinearity -> cell update -> dup'd h stores.
__device__ __forceinline__ void lstm_pointwise(unsigned long long (&acc)[8][4],
                                               float (&cs)[8][2],
                                               uint32_t hrow0)
{
#pragma unroll
    for (int r = 0; r < 8; ++r) {
        float i0, i1, f0, f1, g0, g1, o0, o1;
        unpack2(acc[r][0], i0, i1);
        unpack2(acc[r][1], f0, f1);
        unpack2(acc[r][2], g0, g1);
        unpack2(acc[r][3], o0, o1);
        float c0 = fsig(f0) * cs[r][0] + fsig(i0) * ftanh_(g0);
        float c1 = fsig(f1) * cs[r][1] + fsig(i1) * ftanh_(g1);
        cs[r][0] = c0;
        cs[r][1] = c1;
        float h0 = fsig(o0) * ftanh_(c0);
        float h1 = fsig(o1) * ftanh_(c1);
        asm volatile("st.shared.b64 [%0], %1;" :: "r"(hrow0 + (uint32_t)(r * 8)),
                     "l"(pack2(h0, h0)) : "memory");
        asm volatile("st.shared.b64 [%0], %1;" :: "r"(hrow0 + (uint32_t)(XROWB + r * 8)),
                     "l"(pack2(h1, h1)) : "memory");
    }
}

// ---------------------------------------------------------------------------
__global__ void __launch_bounds__(NTHREAD, 1)
noteaxis_lstm(const float* __restrict__ nf, const float* __restrict__ tg,
              float* __restrict__ out)
{
    extern __shared__ float smem[];
    const int tid  = threadIdx.x;
    const int wgrp = tid >> 2;   // 0..63 : unit pair {2*wgrp, 2*wgrp+1}
    const int bgrp = tid & 3;    // 0..3  : batch rows 8*bgrp..8*bgrp+7
    const int b0   = blockIdx.x * BT;

    const uint32_t sbase = (uint32_t)__cvta_generic_to_shared(smem);
    const uint32_t sx    = sbase;
    const uint32_t sw    = sbase + OFF_W * 4;

    prefetch_chunk(sw, chunk_src(0), tid);
    prefetch_chunk(sw + CHUNK_BYTES, chunk_src(1), tid);

    for (int i = tid; i < OFF_W; i += NTHREAD) smem[i] = 0.0f;
    for (int i = tid; i < GATES; i += NTHREAD) {
        smem[OFF_B0 + i] = g_b0[i];
        smem[OFF_B1 + i] = g_b1[i];
    }
    if (tid < UNITS) smem[OFF_WO + tid] = g_wout[tid];
    if (tid == 0)    smem[OFF_BO] = g_bout[0];

    float cs0[8][2], cs1[8][2];
#pragma unroll
    for (int r = 0; r < 8; ++r) {
        cs0[r][0] = 0.0f; cs0[r][1] = 0.0f;
        cs1[r][0] = 0.0f; cs1[r][1] = 0.0f;
    }

    __syncthreads();

    const uint32_t xoff = bslice(8 * bgrp);
    const uint32_t woff = (uint32_t)wgrp * 8u;
    const uint32_t h0row = sx + (uint32_t)(128 + 2 * wgrp) * XROWB + xoff;
    const uint32_t h1row = sx + (uint32_t)(256 + 2 * wgrp) * XROWB + xoff;

    int pseq = 2;    // next chunk in the 32-chunk step sequence to prefetch
    int gbuf = 0;    // buffer holding the next chunk to consume

    for (int t = 0; t < NSTEP; ++t) {
        // ---- stage x_t (dup'd) into rows 0..127 ---------------------------
#pragma unroll
        for (int i = 0; i < 16; ++i) {
            int idx = tid + i * NTHREAD;     // 0..4095
            int b = idx >> 7;
            int f = idx & 127;
            float v;
            if (f < FDIM)
                v = nf[((b0 + b) * NSTEP + t) * FDIM + f];
            else
                v = (t > 0) ? tg[(b0 + b) * NSTEP + (t - 1)] : 0.0f;
            asm volatile("st.shared.b64 [%0], %1;"
                         :: "r"(sx + (uint32_t)f * XROWB + bslice(b)),
                            "l"(pack2(v, v)) : "memory");
        }

        unsigned long long acc[8][4];

        // ================= layer 0 : gates = [x|h0] @ Wt0 + b0 =============
        {
            const float2* bp = reinterpret_cast<const float2*>(smem + OFF_B0);
#pragma unroll
            for (int g = 0; g < 4; ++g) {
                float2 bv = bp[64 * g + wgrp];
                unsigned long long b2 = pack2(bv.x, bv.y);
#pragma unroll
                for (int r = 0; r < 8; ++r) acc[r][g] = b2;
            }
        }
        for (int ch = 0; ch < NCHUNK; ++ch) {
            asm volatile("cp.async.wait_group 1;" ::: "memory");
            __syncthreads();
            int tbuf = gbuf + 2; if (tbuf >= 3) tbuf -= 3;
            prefetch_chunk(sw + (uint32_t)tbuf * CHUNK_BYTES, chunk_src(pseq), tid);
            if (++pseq == SEQLEN) pseq = 0;
            gemm_chunk(sx + (uint32_t)(ch * KC) * XROWB + xoff,
                       sw + (uint32_t)gbuf * CHUNK_BYTES + woff, acc);
            if (++gbuf == 3) gbuf = 0;
        }
        __syncthreads();
        lstm_pointwise(acc, cs0, h0row);   // h0 -> rows 128..255

        // ================= layer 1 : gates = [h0|h1] @ Wt1 + b1 ============
        {
            const float2* bp = reinterpret_cast<const float2*>(smem + OFF_B1);
#pragma unroll
            for (int g = 0; g < 4; ++g) {
                float2 bv = bp[64 * g + wgrp];
                unsigned long long b2 = pack2(bv.x, bv.y);
#pragma unroll
                for (int r = 0; r < 8; ++r) acc[r][g] = b2;
            }
        }
        for (int ch = 0; ch < NCHUNK; ++ch) {
            asm volatile("cp.async.wait_group 1;" ::: "memory");
            __syncthreads();
            int tbuf = gbuf + 2; if (tbuf >= 3) tbuf -= 3;
            prefetch_chunk(sw + (uint32_t)tbuf * CHUNK_BYTES, chunk_src(pseq), tid);
            if (++pseq == SEQLEN) pseq = 0;
            gemm_chunk(sx + (uint32_t)(128 + ch * KC) * XROWB + xoff,
                       sw + (uint32_t)gbuf * CHUNK_BYTES + woff, acc);
            if (++gbuf == 3) gbuf = 0;
        }
        __syncthreads();
        lstm_pointwise(acc, cs1, h1row);   // h1 -> rows 256..383
        __syncthreads();

        // ---------------- output: sigmoid(h1 . wout + bout) ---------------
        {
            int rowb = tid >> 3;
            int l8   = tid & 7;
            uint32_t so = bslice(rowb) >> 2;
            float s = 0.0f;
#pragma unroll
            for (int jj = 0; jj < 16; ++jj) {
                int u = l8 + 8 * jj;
                s += smem[(256 + u) * XROWF + so] * smem[OFF_WO + u];
            }
            s += __shfl_xor_sync(0xffffffffu, s, 1);
            s += __shfl_xor_sync(0xffffffffu, s, 2);
            s += __shfl_xor_sync(0xffffffffu, s, 4);
            if (l8 == 0)
                out[(b0 + rowb) * NSTEP + t] = fsig(s + smem[OFF_BO]);
        }
    }
}

// ---------------------------------------------------------------------------
extern "C" void kernel_launch(void* const* d_in, const int* in_sizes, int n_in,
                              void* d_out, int out_size)
{
    const float* nf   = (const float*)d_in[0];
    const float* tg   = (const float*)d_in[1];
    const float* wih0 = (const float*)d_in[2];
    const float* whh0 = (const float*)d_in[3];
    const float* bih0 = (const float*)d_in[4];
    const float* bhh0 = (const float*)d_in[5];
    const float* wih1 = (const float*)d_in[6];
    const float* whh1 = (const float*)d_in[7];
    const float* bih1 = (const float*)d_in[8];
    const float* bhh1 = (const float*)d_in[9];
    const float* wout = (const float*)d_in[10];
    const float* bout = (const float*)d_in[11];
    float* out = (float*)d_out;

    cudaFuncSetAttribute(noteaxis_lstm, cudaFuncAttributeMaxDynamicSharedMemorySize, SMEM_BYTES);

    noteaxis_prep<<<(KDIM * GATES + 255) / 256, 256>>>(wih0, whh0, bih0, bhh0,
                                                       wih1, whh1, bih1, bhh1,
                                                       wout, bout);
    noteaxis_lstm<<<NCTA, NTHREAD, SMEM_BYTES>>>(nf, tg, out);
}

// round 9
// speedup vs baseline: 1.0006x; 1.0006x over previous
#include <cuda_runtime.h>
#include <cstdint>

// ---------------------------------------------------------------------------
// NoteAxis: 2-layer LSTM, B=4096, U=128, 128 steps, teacher-forced.
// Persistent fp32 kernel, fma.rn.f32x2 packing two output columns (a unit
// pair) per register; weights load as natural float2, x duplicated in SMEM.
// 128 CTAs x 256 threads; CTA owns 32 batch rows for all 128 steps.
// R8: manual 2-stage software pipeline in the GEMM inner loop — loads for
// iteration k+1 issue before the FMAs of iteration k, hiding the 29-cycle
// LDS latency that bound R5-R7.
// ---------------------------------------------------------------------------

#define B_TOTAL   4096
#define NSTEP     128
#define FDIM      127
#define UNITS     128
#define GATES     512
#define KDIM      256
#define BT        32
#define NCTA      (B_TOTAL / BT)       // 128
#define NTHREAD   256
#define KC        16                   // k rows per weight chunk
#define NCHUNK    (KDIM / KC)          // 16 per layer
#define SEQLEN    (2 * NCHUNK)         // 32 chunks per step (both layers)
#define CHUNK_FLOATS (KC * GATES)      // 8192
#define CHUNK_BYTES  (CHUNK_FLOATS * 4)// 32768

// x region: rows 0..127 = x_t, 128..255 = h0, 256..383 = h1.
// Each row: 32 batch values DUPLICATED ((v,v) f32 pairs) in 4 bank-swizzled
// slices of 8: slice s=b>>3 at byte offset s*64 + (s>>1)*16.
#define XROWF     68                   // floats per row (272 B)
#define XROWB     272
#define NXROW     384

// shared layout (float offsets)
#define OFF_X     0
#define OFF_W     (NXROW * XROWF)              // 26112
#define OFF_B0    (OFF_W + 3 * CHUNK_FLOATS)   // 50688
#define OFF_B1    (OFF_B0 + GATES)             // 51200
#define OFF_WO    (OFF_B1 + GATES)             // 51712
#define OFF_BO    (OFF_WO + UNITS)             // 51840
#define SMEM_FLOATS (OFF_BO + 4)               // 51844
#define SMEM_BYTES  (SMEM_FLOATS * 4)          // 207376 (~202.5 KB)

// ---------------- persistent device scratch (no runtime alloc) -------------
__device__ float g_Wt0[KDIM * GATES];   // [k][c] transposed
__device__ float g_Wt1[KDIM * GATES];
__device__ float g_b0[GATES];           // b_ih + b_hh
__device__ float g_b1[GATES];
__device__ float g_wout[UNITS];
__device__ float g_bout[1];

// ---------------------------------------------------------------------------
__global__ void noteaxis_prep(const float* __restrict__ wih0, const float* __restrict__ whh0,
                              const float* __restrict__ bih0, const float* __restrict__ bhh0,
                              const float* __restrict__ wih1, const float* __restrict__ whh1,
                              const float* __restrict__ bih1, const float* __restrict__ bhh1,
                              const float* __restrict__ wout, const float* __restrict__ bout)
{
    int idx = blockIdx.x * blockDim.x + threadIdx.x;
    if (idx < KDIM * GATES) {
        int k = idx >> 9;
        int c = idx & 511;
        g_Wt0[idx] = (k < UNITS) ? wih0[c * UNITS + k] : whh0[c * UNITS + (k - UNITS)];
        g_Wt1[idx] = (k < UNITS) ? wih1[c * UNITS + k] : whh1[c * UNITS + (k - UNITS)];
    }
    if (idx < GATES) {
        g_b0[idx] = bih0[idx] + bhh0[idx];
        g_b1[idx] = bih1[idx] + bhh1[idx];
    }
    if (idx < UNITS) g_wout[idx] = wout[idx];
    if (idx == 0)    g_bout[0]   = bout[0];
}

// ---------------------------------------------------------------------------
__device__ __forceinline__ float ftanh_(float x) {
    float r;
    asm("tanh.approx.f32 %0, %1;" : "=f"(r) : "f"(x));
    return r;
}
__device__ __forceinline__ float fsig(float x) {
    return fmaf(0.5f, ftanh_(0.5f * x), 0.5f);
}
__device__ __forceinline__ void unpack2(unsigned long long v, float& lo, float& hi) {
    asm("mov.b64 {%0, %1}, %2;" : "=f"(lo), "=f"(hi) : "l"(v));
}
__device__ __forceinline__ unsigned long long pack2(float lo, float hi) {
    unsigned long long v;
    asm("mov.b64 %0, {%1, %2};" : "=l"(v) : "f"(lo), "f"(hi));
    return v;
}

// byte offset of (dup'd) batch element b within an x row
__device__ __forceinline__ uint32_t bslice(int b) {
    int s = b >> 3;
    return (uint32_t)(s * 64 + (s >> 1) * 16 + (b & 7) * 8);
}

// Stage one KC x 512 weight chunk (32 KB) gmem -> smem via cp.async.cg.
__device__ __forceinline__ void prefetch_chunk(uint32_t dst_smem, const float* __restrict__ src, int tid) {
    const char* s = reinterpret_cast<const char*>(src) + tid * 16;
    uint32_t d = dst_smem + tid * 16;
#pragma unroll
    for (int r = 0; r < 8; ++r) {
        asm volatile("cp.async.cg.shared.global [%0], [%1], 16;" :: "r"(d), "l"(s) : "memory");
        d += NTHREAD * 16;
        s += NTHREAD * 16;
    }
    asm volatile("cp.async.commit_group;" ::: "memory");
}

__device__ __forceinline__ const float* chunk_src(int s) {   // s in 0..31
    return (s < NCHUNK) ? (g_Wt0 + (size_t)s * CHUNK_FLOATS)
                        : (g_Wt1 + (size_t)(s - NCHUNK) * CHUNK_FLOATS);
}

// one k-slice of operands
struct KOps {
    unsigned long long x[8];
    unsigned long long w[4];
};

__device__ __forceinline__ void load_k(uint32_t xaddr, uint32_t waddr, KOps& o) {
    asm volatile("ld.shared.v2.u64 {%0, %1}, [%2];" : "=l"(o.x[0]), "=l"(o.x[1]) : "r"(xaddr));
    asm volatile("ld.shared.v2.u64 {%0, %1}, [%2];" : "=l"(o.x[2]), "=l"(o.x[3]) : "r"(xaddr + 16));
    asm volatile("ld.shared.v2.u64 {%0, %1}, [%2];" : "=l"(o.x[4]), "=l"(o.x[5]) : "r"(xaddr + 32));
    asm volatile("ld.shared.v2.u64 {%0, %1}, [%2];" : "=l"(o.x[6]), "=l"(o.x[7]) : "r"(xaddr + 48));
    asm volatile("ld.shared.b64 %0, [%1];" : "=l"(o.w[0]) : "r"(waddr));
    asm volatile("ld.shared.b64 %0, [%1];" : "=l"(o.w[1]) : "r"(waddr + 512));
    asm volatile("ld.shared.b64 %0, [%1];" : "=l"(o.w[2]) : "r"(waddr + 1024));
    asm volatile("ld.shared.b64 %0, [%1];" : "=l"(o.w[3]) : "r"(waddr + 1536));
}

__device__ __forceinline__ void fma_k(const KOps& o, unsigned long long (&acc)[8][4]) {
#pragma unroll
    for (int g = 0; g < 4; ++g)
#pragma unroll
        for (int r = 0; r < 8; ++r)
            asm("fma.rn.f32x2 %0, %1, %2, %0;" : "+l"(acc[r][g]) : "l"(o.x[r]), "l"(o.w[g]));
}

// GEMM over one KC-k chunk, 2-stage software pipelined: loads for k+1 issue
// before the FMAs of k, so the 29-cycle LDS latency is covered by ~32 FMA
// issue slots instead of stalling every iteration.
__device__ __forceinline__ void gemm_chunk(uint32_t xaddr, uint32_t waddr,
                                           unsigned long long (&acc)[8][4])
{
    KOps a, b;
    load_k(xaddr, waddr, a);
#pragma unroll
    for (int kk = 0; kk < KC; kk += 2) {
        xaddr += XROWB;     waddr += GATES * 4;
        load_k(xaddr, waddr, b);          // prefetch k+1
        fma_k(a, acc);                    // consume k
        xaddr += XROWB;     waddr += GATES * 4;
        if (kk + 2 < KC) load_k(xaddr, waddr, a);   // prefetch k+2
        fma_k(b, acc);                    // consume k+1
    }
}

// Gates -> nonlinearity -> cell update -> dup'd h stores.
__device__ __forceinline__ void lstm_pointwise(unsigned long long (&acc)[8][4],
                                               float (&cs)[8][2],
                                               uint32_t hrow0)
{
#pragma unroll
    for (int r = 0; r < 8; ++r) {
        float i0, i1, f0, f1, g0, g1, o0, o1;
        unpack2(acc[r][0], i0, i1);
        unpack2(acc[r][1], f0, f1);
        unpack2(acc[r][2], g0, g1);
        unpack2(acc[r][3], o0, o1);
        float c0 = fsig(f0) * cs[r][0] + fsig(i0) * ftanh_(g0);
        float c1 = fsig(f1) * cs[r][1] + fsig(i1) * ftanh_(g1);
        cs[r][0] = c0;
        cs[r][1] = c1;
        float h0 = fsig(o0) * ftanh_(c0);
        float h1 = fsig(o1) * ftanh_(c1);
        asm volatile("st.shared.b64 [%0], %1;" :: "r"(hrow0 + (uint32_t)(r * 8)),
                     "l"(pack2(h0, h0)) : "memory");
        asm volatile("st.shared.b64 [%0], %1;" :: "r"(hrow0 + (uint32_t)(XROWB + r * 8)),
                     "l"(pack2(h1, h1)) : "memory");
    }
}

// ---------------------------------------------------------------------------
__global__ void __launch_bounds__(NTHREAD, 1)
noteaxis_lstm(const float* __restrict__ nf, const float* __restrict__ tg,
              float* __restrict__ out)
{
    extern __shared__ float smem[];
    const int tid  = threadIdx.x;
    const int wgrp = tid >> 2;   // 0..63 : unit pair {2*wgrp, 2*wgrp+1}
    const int bgrp = tid & 3;    // 0..3  : batch rows 8*bgrp..8*bgrp+7
    const int b0   = blockIdx.x * BT;

    const uint32_t sbase = (uint32_t)__cvta_generic_to_shared(smem);
    const uint32_t sx    = sbase;
    const uint32_t sw    = sbase + OFF_W * 4;

    prefetch_chunk(sw, chunk_src(0), tid);
    prefetch_chunk(sw + CHUNK_BYTES, chunk_src(1), tid);

    for (int i = tid; i < OFF_W; i += NTHREAD) smem[i] = 0.0f;
    for (int i = tid; i < GATES; i += NTHREAD) {
        smem[OFF_B0 + i] = g_b0[i];
        smem[OFF_B1 + i] = g_b1[i];
    }
    if (tid < UNITS) smem[OFF_WO + tid] = g_wout[tid];
    if (tid == 0)    smem[OFF_BO] = g_bout[0];

    float cs0[8][2], cs1[8][2];
#pragma unroll
    for (int r = 0; r < 8; ++r) {
        cs0[r][0] = 0.0f; cs0[r][1] = 0.0f;
        cs1[r][0] = 0.0f; cs1[r][1] = 0.0f;
    }

    __syncthreads();

    const uint32_t xoff = bslice(8 * bgrp);
    const uint32_t woff = (uint32_t)wgrp * 8u;
    const uint32_t h0row = sx + (uint32_t)(128 + 2 * wgrp) * XROWB + xoff;
    const uint32_t h1row = sx + (uint32_t)(256 + 2 * wgrp) * XROWB + xoff;

    int pseq = 2;    // next chunk in the 32-chunk step sequence to prefetch
    int gbuf = 0;    // buffer holding the next chunk to consume

    for (int t = 0; t < NSTEP; ++t) {
        // ---- stage x_t (dup'd) into rows 0..127 ---------------------------
#pragma unroll
        for (int i = 0; i < 16; ++i) {
            int idx = tid + i * NTHREAD;     // 0..4095
            int b = idx >> 7;
            int f = idx & 127;
            float v;
            if (f < FDIM)
                v = nf[((b0 + b) * NSTEP + t) * FDIM + f];
            else
                v = (t > 0) ? tg[(b0 + b) * NSTEP + (t - 1)] : 0.0f;
            asm volatile("st.shared.b64 [%0], %1;"
                         :: "r"(sx + (uint32_t)f * XROWB + bslice(b)),
                            "l"(pack2(v, v)) : "memory");
        }

        unsigned long long acc[8][4];

        // ================= layer 0 : gates = [x|h0] @ Wt0 + b0 =============
        {
            const float2* bp = reinterpret_cast<const float2*>(smem + OFF_B0);
#pragma unroll
            for (int g = 0; g < 4; ++g) {
                float2 bv = bp[64 * g + wgrp];
                unsigned long long b2 = pack2(bv.x, bv.y);
#pragma unroll
                for (int r = 0; r < 8; ++r) acc[r][g] = b2;
            }
        }
        for (int ch = 0; ch < NCHUNK; ++ch) {
            asm volatile("cp.async.wait_group 1;" ::: "memory");
            __syncthreads();
            int tbuf = gbuf + 2; if (tbuf >= 3) tbuf -= 3;
            prefetch_chunk(sw + (uint32_t)tbuf * CHUNK_BYTES, chunk_src(pseq), tid);
            if (++pseq == SEQLEN) pseq = 0;
            gemm_chunk(sx + (uint32_t)(ch * KC) * XROWB + xoff,
                       sw + (uint32_t)gbuf * CHUNK_BYTES + woff, acc);
            if (++gbuf == 3) gbuf = 0;
        }
        __syncthreads();
        lstm_pointwise(acc, cs0, h0row);   // h0 -> rows 128..255

        // ================= layer 1 : gates = [h0|h1] @ Wt1 + b1 ============
        {
            const float2* bp = reinterpret_cast<const float2*>(smem + OFF_B1);
#pragma unroll
            for (int g = 0; g < 4; ++g) {
                float2 bv = bp[64 * g + wgrp];
                unsigned long long b2 = pack2(bv.x, bv.y);
#pragma unroll
                for (int r = 0; r < 8; ++r) acc[r][g] = b2;
            }
        }
        for (int ch = 0; ch < NCHUNK; ++ch) {
            asm volatile("cp.async.wait_group 1;" ::: "memory");
            __syncthreads();
            int tbuf = gbuf + 2; if (tbuf >= 3) tbuf -= 3;
            prefetch_chunk(sw + (uint32_t)tbuf * CHUNK_BYTES, chunk_src(pseq), tid);
            if (++pseq == SEQLEN) pseq = 0;
            gemm_chunk(sx + (uint32_t)(128 + ch * KC) * XROWB + xoff,
                       sw + (uint32_t)gbuf * CHUNK_BYTES + woff, acc);
            if (++gbuf == 3) gbuf = 0;
        }
        __syncthreads();
        lstm_pointwise(acc, cs1, h1row);   // h1 -> rows 256..383
        __syncthreads();

        // ---------------- output: sigmoid(h1 . wout + bout) ---------------
        {
            int rowb = tid >> 3;
            int l8   = tid & 7;
            uint32_t so = bslice(rowb) >> 2;
            float s = 0.0f;
#pragma unroll
            for (int jj = 0; jj < 16; ++jj) {
                int u = l8 + 8 * jj;
                s += smem[(256 + u) * XROWF + so] * smem[OFF_WO + u];
            }
            s += __shfl_xor_sync(0xffffffffu, s, 1);
            s += __shfl_xor_sync(0xffffffffu, s, 2);
            s += __shfl_xor_sync(0xffffffffu, s, 4);
            if (l8 == 0)
                out[(b0 + rowb) * NSTEP + t] = fsig(s + smem[OFF_BO]);
        }
    }
}

// ---------------------------------------------------------------------------
extern "C" void kernel_launch(void* const* d_in, const int* in_sizes, int n_in,
                              void* d_out, int out_size)
{
    const float* nf   = (const float*)d_in[0];
    const float* tg   = (const float*)d_in[1];
    const float* wih0 = (const float*)d_in[2];
    const float* whh0 = (const float*)d_in[3];
    const float* bih0 = (const float*)d_in[4];
    const float* bhh0 = (const float*)d_in[5];
    const float* wih1 = (const float*)d_in[6];
    const float* whh1 = (const float*)d_in[7];
    const float* bih1 = (const float*)d_in[8];
    const float* bhh1 = (const float*)d_in[9];
    const float* wout = (const float*)d_in[10];
    const float* bout = (const float*)d_in[11];
    float* out = (float*)d_out;

    cudaFuncSetAttribute(noteaxis_lstm, cudaFuncAttributeMaxDynamicSharedMemorySize, SMEM_BYTES);

    noteaxis_prep<<<(KDIM * GATES + 255) / 256, 256>>>(wih0, whh0, bih0, bhh0,
                                                       wih1, whh1, bih1, bhh1,
                                                       wout, bout);
    noteaxis_lstm<<<NCTA, NTHREAD, SMEM_BYTES>>>(nf, tg, out);
}